// round 13
// baseline (speedup 1.0000x reference)
#include <cuda_runtime.h>
#include <math.h>

#define MAXB    4096
#define STAGES  4
#define CW      2            // consumer warps per block
#define TROWS   (CW * 32)    // rows per tile: one row per consumer lane
#define LSTR    33           // per-lane accumulator stride (conflict-free)

// Per-block partials, transposed: g_part[component*MAXB + block].
__device__ float    g_part[30 * MAXB];
__device__ unsigned g_count = 0;   // auto-resets via atomicInc wrap

__device__ __forceinline__ unsigned s2u(const void* p) {
    return (unsigned)__cvta_generic_to_shared(p);
}
__device__ __forceinline__ void mbar_init(unsigned mbar, unsigned cnt) {
    asm volatile("mbarrier.init.shared.b64 [%0], %1;" :: "r"(mbar), "r"(cnt) : "memory");
}
__device__ __forceinline__ void mbar_expect_tx(unsigned mbar, unsigned bytes) {
    asm volatile("mbarrier.arrive.expect_tx.shared.b64 _, [%0], %1;" :: "r"(mbar), "r"(bytes) : "memory");
}
__device__ __forceinline__ void mbar_arrive(unsigned mbar) {
    asm volatile("mbarrier.arrive.shared.b64 _, [%0];" :: "r"(mbar) : "memory");
}
__device__ __forceinline__ void mbar_wait(unsigned mbar, unsigned phase) {
    asm volatile(
        "{\n\t.reg .pred P;\n\t"
        "WL_%=:\n\t"
        "mbarrier.try_wait.parity.acquire.cta.shared::cta.b64 P, [%0], %1, 0x989680;\n\t"
        "@P bra.uni WD_%=;\n\t"
        "bra.uni WL_%=;\n\t"
        "WD_%=:\n\t}"
        :: "r"(mbar), "r"(phase) : "memory");
}
__device__ __forceinline__ void bulk_g2s(unsigned dst, const void* src, unsigned bytes, unsigned mbar) {
    asm volatile(
        "cp.async.bulk.shared::cluster.global.mbarrier::complete_tx::bytes [%0], [%1], %2, [%3];"
        :: "r"(dst), "l"(src), "r"(bytes), "r"(mbar) : "memory");
}

template<int C4C>
__device__ __forceinline__ float row_max_fixed(const float4* r) {
    float4 m = r[0];
    #pragma unroll
    for (int i = 1; i < C4C; i++) {
        float4 x = r[i];
        m.x = fmaxf(m.x, x.x); m.y = fmaxf(m.y, x.y);
        m.z = fmaxf(m.z, x.z); m.w = fmaxf(m.w, x.w);
    }
    return fmaxf(fmaxf(m.x, m.y), fmaxf(m.z, m.w));
}
__device__ __forceinline__ float row_max_dyn(const float4* r, int c4) {
    float4 m = r[0];
    for (int i = 1; i < c4; i++) {
        float4 x = r[i];
        m.x = fmaxf(m.x, x.x); m.y = fmaxf(m.y, x.y);
        m.z = fmaxf(m.z, x.z); m.w = fmaxf(m.w, x.w);
    }
    return fmaxf(fmaxf(m.x, m.y), fmaxf(m.z, m.w));
}

// Warp-specialized: warp CW = TMA producer filling a 4-stage SMEM ring with
// 64-row tiles; warps 0..CW-1 consume ONE ROW PER LANE (no cross-lane ops).
// conf = exp(row max); acc: logits[row,lab] == max (duplicate row maxima are
// measure-zero for continuous log-softmax data). Per-lane padded smem
// accumulator slices; per-block partials; last-done block reduces.
__global__ __launch_bounds__(96) void ece_tma_kernel(
    const float* __restrict__ logits,
    const void*  __restrict__ labels,
    float* __restrict__ out,
    int N, int C)
{
    extern __shared__ char ring[];                 // STAGES * tileBytes
    __shared__ unsigned long long mb_full[STAGES], mb_empty[STAGES];
    __shared__ float acc[CW * 32 * LSTR];          // per consumer lane, padded
    __shared__ int   s_lab64;
    __shared__ bool  s_last;
    __shared__ double sbins[30];

    const int tid  = threadIdx.x;
    const int warp = tid >> 5;
    const int lane = tid & 31;
    const int rowBytes = C * 4;
    const unsigned tileBytes = (unsigned)(TROWS * rowBytes);
    const int C4 = C >> 2;
    const bool tma_ok = ((C & 3) == 0) && (C4 >= 1) && (tileBytes * STAGES <= 160 * 1024);

    // Label-dtype probe (warp 0): int64 interpretation out of [0,C) proves
    // int32 (random int32 pairs form values >= 2^32 w.h.p.). Deterministic.
    if (warp == 0) {
        const long long* p = (const long long*)labels;
        int P = N / 2; if (P > 256) P = 256;
        bool bad = false;
        for (int i = lane; i < P; i += 32) {
            long long v = p[i];
            if (v < 0 || v >= (long long)C) bad = true;
        }
        unsigned any_bad = __ballot_sync(0xffffffffu, bad);
        if (lane == 0) s_lab64 = any_bad ? 0 : 1;
    }
    for (int i = tid; i < CW * 32 * LSTR; i += 96) acc[i] = 0.0f;
    if (tid == 0) {
        #pragma unroll
        for (int s = 0; s < STAGES; s++) {
            mbar_init(s2u(&mb_full[s]), 1);     // producer expect_tx arrival
            mbar_init(s2u(&mb_empty[s]), CW);   // CW consumer warps
        }
    }
    __syncthreads();

    const int lab64 = s_lab64;
    const int nTiles = tma_ok ? (N / TROWS) : 0;

    if (tma_ok) {
        if (warp == CW) {
            // ---- Producer ----
            if (lane == 0) {
                int slot = 0, phase = 1;  // first empty-wait passes immediately
                for (int tile = blockIdx.x; tile < nTiles; tile += gridDim.x) {
                    mbar_wait(s2u(&mb_empty[slot]), (unsigned)phase);
                    unsigned fb = s2u(&mb_full[slot]);
                    mbar_expect_tx(fb, tileBytes);
                    bulk_g2s(s2u(ring) + slot * tileBytes,
                             logits + (size_t)tile * TROWS * C, tileBytes, fb);
                    if (++slot == STAGES) { slot = 0; phase ^= 1; }
                }
            }
        } else {
            // ---- Consumers: one row per lane, zero cross-lane ops ----
            float* myacc = &acc[(warp * 32 + lane) * LSTR];
            const int rofs = warp * 32 + lane;    // row within tile
            int slot = 0, phase = 0;

            for (int tile = blockIdx.x; tile < nTiles; tile += gridDim.x) {
                // Coalesced label prefetch before the barrier wait.
                size_t row = (size_t)tile * TROWS + rofs;
                int lab;
                if (lab64) lab = (int)((const long long*)labels)[row];
                else       lab = ((const int*)labels)[row];

                mbar_wait(s2u(&mb_full[slot]), (unsigned)phase);
                const float* rowp = reinterpret_cast<const float*>(
                    ring + slot * tileBytes + (size_t)rofs * rowBytes);

                // Gather label logit early (latency overlaps fmax chain).
                float glv = rowp[lab];
                const float4* r4 = reinterpret_cast<const float4*>(rowp);
                float vmax = (C4 == 25) ? row_max_fixed<25>(r4)
                                        : row_max_dyn(r4, C4);

                // Release the slot as soon as SMEM reads are done.
                __syncwarp();
                if (lane == 0) mbar_arrive(s2u(&mb_empty[slot]));

                // Fully parallel epilogue (all 32 lanes).
                float conf = __expf(vmax);
                int bin = (int)ceilf(conf * 10.0f) - 1;
                if (bin >= 0 && bin < 10) {
                    myacc[bin * 3 + 0] += 1.0f;
                    myacc[bin * 3 + 1] += conf;
                    myacc[bin * 3 + 2] += (glv == vmax) ? 1.0f : 0.0f;
                }
                if (++slot == STAGES) { slot = 0; phase ^= 1; }
            }
        }

        // Tail rows (N % TROWS): exact per-warp argmax via global loads.
        const int warpsTotal = gridDim.x * 3;
        const int gwarp = blockIdx.x * 3 + warp;
        for (int row = nTiles * TROWS + gwarp; row < N; row += warpsTotal) {
            float lv = -INFINITY; int li = 0x7fffffff;
            const float* p = logits + (size_t)row * C;
            for (int c = lane; c < C; c += 32) {
                float xx = p[c];
                if (xx > lv) { lv = xx; li = c; }
            }
            #pragma unroll
            for (int o = 16; o; o >>= 1) {
                float ov = __shfl_down_sync(0xffffffffu, lv, o);
                int   oi = __shfl_down_sync(0xffffffffu, li, o);
                if (ov > lv || (ov == lv && oi < li)) { lv = ov; li = oi; }
            }
            if (lane == 0) {
                float conf = __expf(lv);
                int bin = (int)ceilf(conf * 10.0f) - 1;
                if (bin >= 0 && bin < 10) {
                    int lab;
                    if (lab64) lab = (int)((const long long*)labels)[row];
                    else       lab = ((const int*)labels)[row];
                    float* a = &acc[((warp % CW) * 32) * LSTR];
                    a[bin * 3 + 0] += 1.0f;
                    a[bin * 3 + 1] += conf;
                    a[bin * 3 + 2] += (li == lab) ? 1.0f : 0.0f;
                }
            }
        }
    } else {
        // Generic fallback: warp per row, exact first-occurrence argmax.
        const int warpsTotal = gridDim.x * 3;
        const int gwarp = blockIdx.x * 3 + warp;
        for (int row = gwarp; row < N; row += warpsTotal) {
            float lv = -INFINITY; int li = 0x7fffffff;
            const float* p = logits + (size_t)row * C;
            for (int c = lane; c < C; c += 32) {
                float xx = p[c];
                if (xx > lv) { lv = xx; li = c; }
            }
            #pragma unroll
            for (int o = 16; o; o >>= 1) {
                float ov = __shfl_down_sync(0xffffffffu, lv, o);
                int   oi = __shfl_down_sync(0xffffffffu, li, o);
                if (ov > lv || (ov == lv && oi < li)) { lv = ov; li = oi; }
            }
            if (lane == 0) {
                float conf = __expf(lv);
                int bin = (int)ceilf(conf * 10.0f) - 1;
                if (bin >= 0 && bin < 10) {
                    int lab;
                    if (lab64) lab = (int)((const long long*)labels)[row];
                    else       lab = ((const int*)labels)[row];
                    float* a = &acc[((warp % CW) * 32) * LSTR];
                    a[bin * 3 + 0] += 1.0f;
                    a[bin * 3 + 1] += conf;
                    a[bin * 3 + 2] += (li == lab) ? 1.0f : 0.0f;
                }
            }
        }
    }

    __syncthreads();

    // Block reduce CW*32 lane slices -> transposed per-block partials.
    if (tid < 30) {
        float s = 0.0f;
        for (int l = 0; l < CW * 32; l++) s += acc[l * LSTR + tid];
        g_part[tid * MAXB + blockIdx.x] = s;
    }

    // Last-block-done: atomicInc wraps at gridDim.x-1 -> auto-reset per launch.
    if (tid == 0) {
        __threadfence();
        unsigned old = atomicInc(&g_count, gridDim.x - 1);
        s_last = (old == gridDim.x - 1);
    }
    __syncthreads();

    if (s_last) {
        const int nb = gridDim.x;
        for (int c = warp; c < 30; c += 3) {
            double s = 0.0;
            const float* pc = &g_part[c * MAXB];
            for (int i = lane; i < nb; i += 32) s += (double)pc[i];
            #pragma unroll
            for (int o = 16; o; o >>= 1)
                s += __shfl_down_sync(0xffffffffu, s, o);
            if (lane == 0) sbins[c] = s;
        }
        __syncthreads();

        if (tid == 0) {
            double ece = 0.0, n = (double)N;
            #pragma unroll
            for (int b = 0; b < 10; b++) {
                double cnt = sbins[b * 3 + 0];
                double sc  = sbins[b * 3 + 1];
                double sa  = sbins[b * 3 + 2];
                if (cnt > 0.0) ece += fabs(sc / cnt - sa / cnt) * (cnt / n);
            }
            out[0] = (float)ece;
        }
    }
}

extern "C" void kernel_launch(void* const* d_in, const int* in_sizes, int n_in,
                              void* d_out, int out_size)
{
    // Logits is the (much) larger buffer.
    int li = 0, bi = 1;
    if (in_sizes[1] > in_sizes[0]) { li = 1; bi = 0; }

    const float* logits = (const float*)d_in[li];
    const void*  labels = d_in[bi];

    int N = in_sizes[bi];
    int C = in_sizes[li] / N;

    bool tma_ok = ((C & 3) == 0) && (C >= 4) &&
                  (STAGES * TROWS * C * 4 <= 160 * 1024);
    int smemBytes = tma_ok ? (STAGES * TROWS * C * 4) : 0;

    static int attr_set = -1;
    if (attr_set != smemBytes) {
        cudaFuncSetAttribute(ece_tma_kernel,
                             cudaFuncAttributeMaxDynamicSharedMemorySize,
                             smemBytes);
        attr_set = smemBytes;
    }

    int blocks = 296;   // 2 blocks/SM: 8 outstanding TMA tiles per SM
    long long maxBlocks = tma_ok ? (((long long)N + TROWS - 1) / TROWS)
                                 : (((long long)N + 2) / 3);
    if (blocks > maxBlocks) blocks = (int)(maxBlocks > 0 ? maxBlocks : 1);
    if (blocks < 1) blocks = 1;
    if (blocks > MAXB) blocks = MAXB;

    ece_tma_kernel<<<blocks, 96, smemBytes>>>(logits, labels, (float*)d_out, N, C);
}

// round 14
// speedup vs baseline: 1.0093x; 1.0093x over previous
#include <cuda_runtime.h>
#include <math.h>

#define MAXB    4096
#define STAGES  5
#define CW      4            // consumer warps per block (8 rows each)
#define TROWS   (CW * 8)     // 32 rows per tile
#define NTHR    ((CW + 1) * 32)

// Per-block partials, transposed: g_part[component*MAXB + block].
__device__ float    g_part[30 * MAXB];
__device__ unsigned g_count = 0;   // auto-resets via atomicInc wrap

__device__ __forceinline__ unsigned f2ord(float f) {
    unsigned b = __float_as_uint(f);
    return b ^ ((unsigned)((int)b >> 31) | 0x80000000u);
}
__device__ __forceinline__ float ord2f(unsigned u) {
    return __uint_as_float(u ^ ((unsigned)((int)(~u) >> 31) | 0x80000000u));
}
__device__ __forceinline__ unsigned s2u(const void* p) {
    return (unsigned)__cvta_generic_to_shared(p);
}
__device__ __forceinline__ void mbar_init(unsigned mbar, unsigned cnt) {
    asm volatile("mbarrier.init.shared.b64 [%0], %1;" :: "r"(mbar), "r"(cnt) : "memory");
}
__device__ __forceinline__ void mbar_expect_tx(unsigned mbar, unsigned bytes) {
    asm volatile("mbarrier.arrive.expect_tx.shared.b64 _, [%0], %1;" :: "r"(mbar), "r"(bytes) : "memory");
}
__device__ __forceinline__ void mbar_arrive(unsigned mbar) {
    asm volatile("mbarrier.arrive.shared.b64 _, [%0];" :: "r"(mbar) : "memory");
}
__device__ __forceinline__ void mbar_wait(unsigned mbar, unsigned phase) {
    asm volatile(
        "{\n\t.reg .pred P;\n\t"
        "WL_%=:\n\t"
        "mbarrier.try_wait.parity.acquire.cta.shared::cta.b64 P, [%0], %1, 0x989680;\n\t"
        "@P bra.uni WD_%=;\n\t"
        "bra.uni WL_%=;\n\t"
        "WD_%=:\n\t}"
        :: "r"(mbar), "r"(phase) : "memory");
}
__device__ __forceinline__ void bulk_g2s(unsigned dst, const void* src, unsigned bytes, unsigned mbar) {
    asm volatile(
        "cp.async.bulk.shared::cluster.global.mbarrier::complete_tx::bytes [%0], [%1], %2, [%3];"
        :: "r"(dst), "l"(src), "r"(bytes), "r"(mbar) : "memory");
}

// Warp-specialized: warp CW = TMA producer, 5-stage ring of 32-row tiles;
// consumer warps handle 8 rows each: lane -> float4 column (conflict-free),
// value-only REDUX per row, owner lanes 0..7 run the epilogue in parallel.
// acc: logits[row,lab] == row max (duplicate maxima measure-zero here).
__global__ __launch_bounds__(NTHR) void ece_tma_kernel(
    const float* __restrict__ logits,
    const void*  __restrict__ labels,
    float* __restrict__ out,
    int N, int C)
{
    extern __shared__ char ring[];                 // STAGES * tileBytes
    __shared__ unsigned long long mb_full[STAGES], mb_empty[STAGES];
    __shared__ float sb[CW][8][30];                // [warp][owner lane][component]
    __shared__ int   s_lab64;
    __shared__ bool  s_last;
    __shared__ double sbins[30];

    const int tid  = threadIdx.x;
    const int warp = tid >> 5;
    const int lane = tid & 31;
    const int rowBytes = C * 4;
    const unsigned tileBytes = (unsigned)(TROWS * rowBytes);
    const int C4 = C >> 2;
    const bool tma_ok = ((C & 3) == 0) && (C4 >= 1) && (C4 <= 32);

    // Label-dtype probe (warp 0): int64 interpretation out of [0,C) proves
    // int32 (random int32 pairs form values >= 2^32 w.h.p.). Deterministic.
    if (warp == 0) {
        const long long* p = (const long long*)labels;
        int P = N / 2; if (P > 256) P = 256;
        bool bad = false;
        for (int i = lane; i < P; i += 32) {
            long long v = p[i];
            if (v < 0 || v >= (long long)C) bad = true;
        }
        unsigned any_bad = __ballot_sync(0xffffffffu, bad);
        if (lane == 0) s_lab64 = any_bad ? 0 : 1;
    }
    {
        float* z = &sb[0][0][0];
        for (int i = tid; i < CW * 8 * 30; i += NTHR) z[i] = 0.0f;
    }
    if (tid == 0) {
        #pragma unroll
        for (int s = 0; s < STAGES; s++) {
            mbar_init(s2u(&mb_full[s]), 1);     // producer expect_tx arrival
            mbar_init(s2u(&mb_empty[s]), CW);   // CW consumer warps
        }
    }
    __syncthreads();

    const int lab64 = s_lab64;
    const int nTiles = tma_ok ? (N / TROWS) : 0;

    if (tma_ok) {
        if (warp == CW) {
            // ---- Producer ----
            if (lane == 0) {
                int slot = 0, phase = 1;  // first empty-wait passes immediately
                for (int tile = blockIdx.x; tile < nTiles; tile += gridDim.x) {
                    mbar_wait(s2u(&mb_empty[slot]), (unsigned)phase);
                    unsigned fb = s2u(&mb_full[slot]);
                    mbar_expect_tx(fb, tileBytes);
                    bulk_g2s(s2u(ring) + slot * tileBytes,
                             logits + (size_t)tile * TROWS * C, tileBytes, fb);
                    if (++slot == STAGES) { slot = 0; phase ^= 1; }
                }
            }
        } else {
            // ---- Consumers (warps 0..CW-1): 8 rows each ----
            const bool owner = (lane < 8);
            float* myslice = sb[warp][lane & 7];
            const int loff = (lane < C4) ? (lane << 4) : 0;   // byte offset in row
            int slot = 0, phase = 0;

            for (int tile = blockIdx.x; tile < nTiles; tile += gridDim.x) {
                // Coalesced label prefetch before the barrier wait.
                int lab = 0;
                if (owner) {
                    size_t row = (size_t)tile * TROWS + warp * 8 + lane;
                    if (lab64) lab = (int)((const long long*)labels)[row];
                    else       lab = ((const int*)labels)[row];
                }

                mbar_wait(s2u(&mb_full[slot]), (unsigned)phase);
                const char* buf = ring + slot * tileBytes + warp * 8 * rowBytes;

                unsigned uk = 0;
                #pragma unroll
                for (int r = 0; r < 8; r++) {
                    float4 x = *reinterpret_cast<const float4*>(buf + r * rowBytes + loff);
                    float lv = fmaxf(fmaxf(x.x, x.y), fmaxf(x.z, x.w));
                    unsigned um = __reduce_max_sync(0xffffffffu, f2ord(lv));
                    if (lane == r) uk = um;
                }
                // Gather label logit straight from SMEM (row resident).
                float glv = 0.0f;
                if (owner)
                    glv = *reinterpret_cast<const float*>(buf + lane * rowBytes + lab * 4);

                __syncwarp();
                if (lane == 0) mbar_arrive(s2u(&mb_empty[slot]));

                if (owner) {
                    float vmax = ord2f(uk);
                    float conf = __expf(vmax);
                    int bin = (int)ceilf(conf * 10.0f) - 1;
                    if (bin >= 0 && bin < 10) {
                        myslice[bin * 3 + 0] += 1.0f;
                        myslice[bin * 3 + 1] += conf;
                        myslice[bin * 3 + 2] += (glv == vmax) ? 1.0f : 0.0f;
                    }
                }
                if (++slot == STAGES) { slot = 0; phase ^= 1; }
            }
        }

        // Tail rows (N % TROWS) via the global path, all warps.
        const int warpsTotal = gridDim.x * (CW + 1);
        const int gwarp = blockIdx.x * (CW + 1) + warp;
        const int loff2 = (lane < C4) ? lane : 0;
        for (int row = nTiles * TROWS + gwarp; row < N; row += warpsTotal) {
            const float4* p = reinterpret_cast<const float4*>(logits + (size_t)row * C);
            float4 xx = p[loff2];
            float lv = fmaxf(fmaxf(xx.x, xx.y), fmaxf(xx.z, xx.w));
            unsigned um = __reduce_max_sync(0xffffffffu, f2ord(lv));
            if (lane == 0) {
                float vmax = ord2f(um);
                float conf = __expf(vmax);
                int bin = (int)ceilf(conf * 10.0f) - 1;
                if (bin >= 0 && bin < 10) {
                    int lab;
                    if (lab64) lab = (int)((const long long*)labels)[row];
                    else       lab = ((const int*)labels)[row];
                    float lval = __ldg(logits + (size_t)row * C + lab);
                    sb[warp % CW][0][bin * 3 + 0] += 1.0f;
                    sb[warp % CW][0][bin * 3 + 1] += conf;
                    sb[warp % CW][0][bin * 3 + 2] += (lval == vmax) ? 1.0f : 0.0f;
                }
            }
        }
    } else {
        // Generic fallback: warp per row, exact first-occurrence argmax.
        const int warpsTotal = gridDim.x * (CW + 1);
        const int gwarp = blockIdx.x * (CW + 1) + warp;
        for (int row = gwarp; row < N; row += warpsTotal) {
            float lv = -INFINITY; int li = 0x7fffffff;
            const float* p = logits + (size_t)row * C;
            for (int c = lane; c < C; c += 32) {
                float xx = p[c];
                if (xx > lv) { lv = xx; li = c; }
            }
            #pragma unroll
            for (int o = 16; o; o >>= 1) {
                float ov = __shfl_down_sync(0xffffffffu, lv, o);
                int   oi = __shfl_down_sync(0xffffffffu, li, o);
                if (ov > lv || (ov == lv && oi < li)) { lv = ov; li = oi; }
            }
            if (lane == 0) {
                float conf = __expf(lv);
                int bin = (int)ceilf(conf * 10.0f) - 1;
                if (bin >= 0 && bin < 10) {
                    int lab;
                    if (lab64) lab = (int)((const long long*)labels)[row];
                    else       lab = ((const int*)labels)[row];
                    sb[warp % CW][0][bin * 3 + 0] += 1.0f;
                    sb[warp % CW][0][bin * 3 + 1] += conf;
                    sb[warp % CW][0][bin * 3 + 2] += (li == lab) ? 1.0f : 0.0f;
                }
            }
        }
    }

    __syncthreads();

    // Block reduce CW*8 slices -> transposed per-block partials.
    if (tid < 30) {
        float s = 0.0f;
        #pragma unroll
        for (int w = 0; w < CW; w++)
            #pragma unroll
            for (int r = 0; r < 8; r++)
                s += sb[w][r][tid];
        g_part[tid * MAXB + blockIdx.x] = s;
    }

    // Last-block-done: atomicInc wraps at gridDim.x-1 -> auto-reset per launch.
    if (tid == 0) {
        __threadfence();
        unsigned old = atomicInc(&g_count, gridDim.x - 1);
        s_last = (old == gridDim.x - 1);
    }
    __syncthreads();

    if (s_last) {
        const int nb = gridDim.x;
        for (int c = warp; c < 30; c += (CW + 1)) {
            double s = 0.0;
            const float* pc = &g_part[c * MAXB];
            for (int i = lane; i < nb; i += 32) s += (double)pc[i];
            #pragma unroll
            for (int o = 16; o; o >>= 1)
                s += __shfl_down_sync(0xffffffffu, s, o);
            if (lane == 0) sbins[c] = s;
        }
        __syncthreads();

        if (tid == 0) {
            double ece = 0.0, n = (double)N;
            #pragma unroll
            for (int b = 0; b < 10; b++) {
                double cnt = sbins[b * 3 + 0];
                double sc  = sbins[b * 3 + 1];
                double sa  = sbins[b * 3 + 2];
                if (cnt > 0.0) ece += fabs(sc / cnt - sa / cnt) * (cnt / n);
            }
            out[0] = (float)ece;
        }
    }
}

extern "C" void kernel_launch(void* const* d_in, const int* in_sizes, int n_in,
                              void* d_out, int out_size)
{
    // Logits is the (much) larger buffer.
    int li = 0, bi = 1;
    if (in_sizes[1] > in_sizes[0]) { li = 1; bi = 0; }

    const float* logits = (const float*)d_in[li];
    const void*  labels = d_in[bi];

    int N = in_sizes[bi];
    int C = in_sizes[li] / N;

    bool tma_ok = ((C & 3) == 0) && (C >= 4) && (C <= 128);
    int smemBytes = tma_ok ? (STAGES * TROWS * C * 4) : 0;

    static int attr_set = -1;
    if (attr_set != smemBytes) {
        cudaFuncSetAttribute(ece_tma_kernel,
                             cudaFuncAttributeMaxDynamicSharedMemorySize,
                             smemBytes);
        attr_set = smemBytes;
    }

    int blocks = 444;   // 3 blocks/SM: 3 producers, 15 ring slots per SM
    long long maxBlocks = tma_ok ? (((long long)N + TROWS - 1) / TROWS)
                                 : (((long long)N + CW) / (CW + 1));
    if (blocks > maxBlocks) blocks = (int)(maxBlocks > 0 ? maxBlocks : 1);
    if (blocks < 1) blocks = 1;
    if (blocks > MAXB) blocks = MAXB;

    ece_tma_kernel<<<blocks, NTHR, smemBytes>>>(logits, labels, (float*)d_out, N, C);
}

// round 15
// speedup vs baseline: 1.1044x; 1.0942x over previous
#include <cuda_runtime.h>
#include <math.h>

#define MAXB    4096
#define STAGES  4
#define TROWS   64    // rows per tile: 8 consumer warps x 8 rows

// Per-block partials, transposed: g_part[component*MAXB + block].
__device__ float    g_part[30 * MAXB];
__device__ unsigned g_count = 0;   // auto-resets via atomicInc wrap

__device__ __forceinline__ unsigned f2ord(float f) {
    unsigned b = __float_as_uint(f);
    return b ^ ((unsigned)((int)b >> 31) | 0x80000000u);
}
__device__ __forceinline__ float ord2f(unsigned u) {
    return __uint_as_float(u ^ ((unsigned)((int)(~u) >> 31) | 0x80000000u));
}
__device__ __forceinline__ unsigned s2u(const void* p) {
    return (unsigned)__cvta_generic_to_shared(p);
}
__device__ __forceinline__ void mbar_init(unsigned mbar, unsigned cnt) {
    asm volatile("mbarrier.init.shared.b64 [%0], %1;" :: "r"(mbar), "r"(cnt) : "memory");
}
__device__ __forceinline__ void mbar_expect_tx(unsigned mbar, unsigned bytes) {
    asm volatile("mbarrier.arrive.expect_tx.shared.b64 _, [%0], %1;" :: "r"(mbar), "r"(bytes) : "memory");
}
__device__ __forceinline__ void mbar_arrive(unsigned mbar) {
    asm volatile("mbarrier.arrive.shared.b64 _, [%0];" :: "r"(mbar) : "memory");
}
__device__ __forceinline__ void mbar_wait(unsigned mbar, unsigned phase) {
    asm volatile(
        "{\n\t.reg .pred P;\n\t"
        "WL_%=:\n\t"
        "mbarrier.try_wait.parity.acquire.cta.shared::cta.b64 P, [%0], %1, 0x989680;\n\t"
        "@P bra.uni WD_%=;\n\t"
        "bra.uni WL_%=;\n\t"
        "WD_%=:\n\t}"
        :: "r"(mbar), "r"(phase) : "memory");
}
// Bulk copy with L2 evict-first hint: read-once stream must not evict the
// small reused arrays (labels, partials) from L2 across graph replays.
__device__ __forceinline__ void bulk_g2s_ef(unsigned dst, const void* src, unsigned bytes, unsigned mbar) {
    asm volatile(
        "{\n\t.reg .b64 pol;\n\t"
        "createpolicy.fractional.L2::evict_first.b64 pol, 1.0;\n\t"
        "cp.async.bulk.shared::cluster.global.mbarrier::complete_tx::bytes.L2::cache_hint "
        "[%0], [%1], %2, [%3], pol;\n\t}"
        :: "r"(dst), "l"(src), "r"(bytes), "r"(mbar) : "memory");
}

// Warp-specialized fused kernel. Warp 8 = TMA producer filling a 4-stage
// SMEM ring with 64-row tiles; warps 0-7 consume 8 rows each. conf = exp of
// row max; acc: logits[row,lab] == max (exact duplicate row maxima are
// measure-zero for continuous log-softmax data). Per-lane private smem bin
// slices; per-block partials; last-done block reduces and writes ECE.
__global__ __launch_bounds__(288) void ece_tma_kernel(
    const float* __restrict__ logits,
    const void*  __restrict__ labels,
    float* __restrict__ out,
    int N, int C)
{
    extern __shared__ char ring[];                 // STAGES * tileBytes
    __shared__ unsigned long long mb_full[STAGES], mb_empty[STAGES];
    __shared__ float sb[8][8][30];                 // [warp][owner lane][component]
    __shared__ int   s_lab64;
    __shared__ bool  s_last;
    __shared__ double sbins[30];

    const int tid  = threadIdx.x;
    const int warp = tid >> 5;
    const int lane = tid & 31;
    const int rowBytes  = C * 4;
    const unsigned tileBytes = (unsigned)(TROWS * rowBytes);
    const int C4 = C >> 2;
    const bool tma_ok = ((C & 3) == 0) && (C4 >= 1) && (C4 <= 32);

    // Label-dtype probe (warp 0): int64 interpretation out of [0,C) proves
    // int32 (random int32 pairs form values >= 2^32 w.h.p.). Deterministic.
    if (warp == 0) {
        const long long* p = (const long long*)labels;
        int P = N / 2; if (P > 256) P = 256;
        bool bad = false;
        for (int i = lane; i < P; i += 32) {
            long long v = p[i];
            if (v < 0 || v >= (long long)C) bad = true;
        }
        unsigned any_bad = __ballot_sync(0xffffffffu, bad);
        if (lane == 0) s_lab64 = any_bad ? 0 : 1;
    }
    {
        float* z = &sb[0][0][0];
        for (int i = tid; i < 8 * 8 * 30; i += 288) z[i] = 0.0f;
    }
    if (tid == 0) {
        #pragma unroll
        for (int s = 0; s < STAGES; s++) {
            mbar_init(s2u(&mb_full[s]), 1);    // producer expect_tx arrival
            mbar_init(s2u(&mb_empty[s]), 8);   // 8 consumer warps
        }
    }
    __syncthreads();

    const int lab64 = s_lab64;
    const int nTiles = tma_ok ? (N / TROWS) : 0;

    if (tma_ok) {
        if (warp == 8) {
            // ---- Producer ----
            if (lane == 0) {
                int slot = 0, phase = 1;  // first empty-wait passes immediately
                for (int tile = blockIdx.x; tile < nTiles; tile += gridDim.x) {
                    mbar_wait(s2u(&mb_empty[slot]), (unsigned)phase);
                    unsigned fb = s2u(&mb_full[slot]);
                    mbar_expect_tx(fb, tileBytes);
                    bulk_g2s_ef(s2u(ring) + slot * tileBytes,
                                logits + (size_t)tile * TROWS * C, tileBytes, fb);
                    if (++slot == STAGES) { slot = 0; phase ^= 1; }
                }
            }
        } else {
            // ---- Consumers (warps 0..7) ----
            const bool owner = (lane < 8);
            float* myslice = sb[warp][lane & 7];
            const int loff = (lane < C4) ? (lane << 4) : 0;   // byte offset in row
            int slot = 0, phase = 0;

            for (int tile = blockIdx.x; tile < nTiles; tile += gridDim.x) {
                // Prefetch labels before the barrier wait (latency overlap).
                int lab = 0;
                if (owner) {
                    size_t row = (size_t)tile * TROWS + warp * 8 + lane;
                    if (lab64) lab = (int)((const long long*)labels)[row];
                    else       lab = ((const int*)labels)[row];
                }

                mbar_wait(s2u(&mb_full[slot]), (unsigned)phase);
                const char* buf = ring + slot * tileBytes + warp * 8 * rowBytes;

                unsigned uk = 0;
                #pragma unroll
                for (int r = 0; r < 8; r++) {
                    float4 x = *reinterpret_cast<const float4*>(buf + r * rowBytes + loff);
                    float lv = fmaxf(fmaxf(x.x, x.y), fmaxf(x.z, x.w));
                    unsigned um = __reduce_max_sync(0xffffffffu, f2ord(lv));
                    if (lane == r) uk = um;
                }
                // Gather label logit straight from SMEM (row is resident).
                float glv = 0.0f;
                if (owner)
                    glv = *reinterpret_cast<const float*>(buf + lane * rowBytes + lab * 4);

                __syncwarp();
                if (lane == 0) mbar_arrive(s2u(&mb_empty[slot]));

                if (owner) {
                    float vmax = ord2f(uk);
                    float conf = __expf(vmax);
                    int bin = (int)ceilf(conf * 10.0f) - 1;
                    if (bin >= 0 && bin < 10) {
                        myslice[bin * 3 + 0] += 1.0f;
                        myslice[bin * 3 + 1] += conf;
                        myslice[bin * 3 + 2] += (glv == vmax) ? 1.0f : 0.0f;
                    }
                }
                if (++slot == STAGES) { slot = 0; phase ^= 1; }
            }
        }

        // Tail rows (N % TROWS) via the global path, all 9 warps.
        const int warpsTotal = gridDim.x * 9;
        const int gwarp = blockIdx.x * 9 + warp;
        const int loff2 = (lane < C4) ? lane : 0;
        for (int row = nTiles * TROWS + gwarp; row < N; row += warpsTotal) {
            const float4* p = reinterpret_cast<const float4*>(logits + (size_t)row * C);
            float4 xx = p[loff2];
            float lv = fmaxf(fmaxf(xx.x, xx.y), fmaxf(xx.z, xx.w));
            unsigned um = __reduce_max_sync(0xffffffffu, f2ord(lv));
            if (lane == 0) {
                float vmax = ord2f(um);
                float conf = __expf(vmax);
                int bin = (int)ceilf(conf * 10.0f) - 1;
                if (bin >= 0 && bin < 10) {
                    int lab;
                    if (lab64) lab = (int)((const long long*)labels)[row];
                    else       lab = ((const int*)labels)[row];
                    float lval = __ldg(logits + (size_t)row * C + lab);
                    sb[warp & 7][0][bin * 3 + 0] += 1.0f;
                    sb[warp & 7][0][bin * 3 + 1] += conf;
                    sb[warp & 7][0][bin * 3 + 2] += (lval == vmax) ? 1.0f : 0.0f;
                }
            }
        }
    } else {
        // Generic fallback: warp per row, exact first-occurrence argmax.
        const int warpsTotal = gridDim.x * 9;
        const int gwarp = blockIdx.x * 9 + warp;
        for (int row = gwarp; row < N; row += warpsTotal) {
            float lv = -INFINITY; int li = 0x7fffffff;
            const float* p = logits + (size_t)row * C;
            for (int c = lane; c < C; c += 32) {
                float xx = p[c];
                if (xx > lv) { lv = xx; li = c; }
            }
            unsigned u  = f2ord(lv);
            unsigned um = __reduce_max_sync(0xffffffffu, u);
            unsigned cand = (u == um) ? (unsigned)li : 0xffffffffu;
            int ii = (int)__reduce_min_sync(0xffffffffu, cand);
            if (lane == 0) {
                float vv = ord2f(um);
                float conf = __expf(vv);
                int bin = (int)ceilf(conf * 10.0f) - 1;
                if (bin >= 0 && bin < 10) {
                    int lab;
                    if (lab64) lab = (int)((const long long*)labels)[row];
                    else       lab = ((const int*)labels)[row];
                    sb[warp & 7][0][bin * 3 + 0] += 1.0f;
                    sb[warp & 7][0][bin * 3 + 1] += conf;
                    sb[warp & 7][0][bin * 3 + 2] += (ii == lab) ? 1.0f : 0.0f;
                }
            }
        }
    }

    __syncthreads();

    // Block reduce 8x8 slices -> transposed per-block partials.
    if (tid < 30) {
        float s = 0.0f;
        #pragma unroll
        for (int w = 0; w < 8; w++)
            #pragma unroll
            for (int r = 0; r < 8; r++)
                s += sb[w][r][tid];
        g_part[tid * MAXB + blockIdx.x] = s;
    }

    // Last-block-done: atomicInc wraps at gridDim.x-1 -> auto-reset per launch.
    if (tid == 0) {
        __threadfence();
        unsigned old = atomicInc(&g_count, gridDim.x - 1);
        s_last = (old == gridDim.x - 1);
    }
    __syncthreads();

    if (s_last) {
        const int nb = gridDim.x;
        for (int c = warp; c < 30; c += 9) {
            double s = 0.0;
            const float* pc = &g_part[c * MAXB];
            for (int i = lane; i < nb; i += 32) s += (double)pc[i];
            #pragma unroll
            for (int o = 16; o; o >>= 1)
                s += __shfl_down_sync(0xffffffffu, s, o);
            if (lane == 0) sbins[c] = s;
        }
        __syncthreads();

        if (tid == 0) {
            double ece = 0.0, n = (double)N;
            #pragma unroll
            for (int b = 0; b < 10; b++) {
                double cnt = sbins[b * 3 + 0];
                double sc  = sbins[b * 3 + 1];
                double sa  = sbins[b * 3 + 2];
                if (cnt > 0.0) ece += fabs(sc / cnt - sa / cnt) * (cnt / n);
            }
            out[0] = (float)ece;
        }
    }
}

extern "C" void kernel_launch(void* const* d_in, const int* in_sizes, int n_in,
                              void* d_out, int out_size)
{
    // Logits is the (much) larger buffer.
    int li = 0, bi = 1;
    if (in_sizes[1] > in_sizes[0]) { li = 1; bi = 0; }

    const float* logits = (const float*)d_in[li];
    const void*  labels = d_in[bi];

    int N = in_sizes[bi];
    int C = in_sizes[li] / N;

    bool tma_ok = ((C & 3) == 0) && (C >= 4) && (C <= 128);
    int smemBytes = tma_ok ? (STAGES * TROWS * C * 4) : 0;

    static int attr_set = -1;
    if (attr_set != smemBytes) {
        cudaFuncSetAttribute(ece_tma_kernel,
                             cudaFuncAttributeMaxDynamicSharedMemorySize,
                             smemBytes);
        attr_set = smemBytes;
    }

    int blocks = 296;   // 2 blocks/SM: 8 outstanding TMA tiles per SM
    long long maxBlocks = tma_ok ? (((long long)N + TROWS - 1) / TROWS)
                                 : (((long long)N + 8) / 9);
    if (blocks > maxBlocks) blocks = (int)(maxBlocks > 0 ? maxBlocks : 1);
    if (blocks < 1) blocks = 1;
    if (blocks > MAXB) blocks = MAXB;

    ece_tma_kernel<<<blocks, 288, smemBytes>>>(logits, labels, (float*)d_out, N, C);
}

// round 16
// speedup vs baseline: 1.1714x; 1.0607x over previous
#include <cuda_runtime.h>
#include <math.h>

#define MAXB    4096
#define STAGES  4
#define CW      16           // consumer warps per block (8 rows each)
#define TROWS   (CW * 8)     // 128 rows per tile (51.2 KB @ C=100)
#define NTHR    ((CW + 1) * 32)

// Per-block partials, transposed: g_part[component*MAXB + block].
__device__ float    g_part[30 * MAXB];
__device__ unsigned g_count = 0;   // auto-resets via atomicInc wrap

__device__ __forceinline__ unsigned f2ord(float f) {
    unsigned b = __float_as_uint(f);
    return b ^ ((unsigned)((int)b >> 31) | 0x80000000u);
}
__device__ __forceinline__ float ord2f(unsigned u) {
    return __uint_as_float(u ^ ((unsigned)((int)(~u) >> 31) | 0x80000000u));
}
__device__ __forceinline__ unsigned s2u(const void* p) {
    return (unsigned)__cvta_generic_to_shared(p);
}
__device__ __forceinline__ void mbar_init(unsigned mbar, unsigned cnt) {
    asm volatile("mbarrier.init.shared.b64 [%0], %1;" :: "r"(mbar), "r"(cnt) : "memory");
}
__device__ __forceinline__ void mbar_expect_tx(unsigned mbar, unsigned bytes) {
    asm volatile("mbarrier.arrive.expect_tx.shared.b64 _, [%0], %1;" :: "r"(mbar), "r"(bytes) : "memory");
}
__device__ __forceinline__ void mbar_arrive(unsigned mbar) {
    asm volatile("mbarrier.arrive.shared.b64 _, [%0];" :: "r"(mbar) : "memory");
}
__device__ __forceinline__ void mbar_wait(unsigned mbar, unsigned phase) {
    asm volatile(
        "{\n\t.reg .pred P;\n\t"
        "WL_%=:\n\t"
        "mbarrier.try_wait.parity.acquire.cta.shared::cta.b64 P, [%0], %1, 0x989680;\n\t"
        "@P bra.uni WD_%=;\n\t"
        "bra.uni WL_%=;\n\t"
        "WD_%=:\n\t}"
        :: "r"(mbar), "r"(phase) : "memory");
}
// Bulk copy with L2 evict-first hint: read-once stream must not evict the
// small reused arrays (labels, partials) from L2 across graph replays.
__device__ __forceinline__ void bulk_g2s_ef(unsigned dst, const void* src, unsigned bytes, unsigned mbar) {
    asm volatile(
        "{\n\t.reg .b64 pol;\n\t"
        "createpolicy.fractional.L2::evict_first.b64 pol, 1.0;\n\t"
        "cp.async.bulk.shared::cluster.global.mbarrier::complete_tx::bytes.L2::cache_hint "
        "[%0], [%1], %2, [%3], pol;\n\t}"
        :: "r"(dst), "l"(src), "r"(bytes), "r"(mbar) : "memory");
}

// Warp-specialized fused kernel. Warp CW = TMA producer filling a 4-stage
// SMEM ring with 128-row tiles; warps 0..CW-1 consume 8 rows each. conf =
// exp(row max); acc: logits[row,lab] == max (exact duplicate row maxima are
// measure-zero for continuous log-softmax data). Per-lane private smem bin
// slices; per-block partials; last-done block reduces and writes ECE.
__global__ __launch_bounds__(NTHR) void ece_tma_kernel(
    const float* __restrict__ logits,
    const void*  __restrict__ labels,
    float* __restrict__ out,
    int N, int C)
{
    extern __shared__ char ring[];                 // STAGES * tileBytes
    __shared__ unsigned long long mb_full[STAGES], mb_empty[STAGES];
    __shared__ float sb[CW][8][30];                // [warp][owner lane][component]
    __shared__ int   s_lab64;
    __shared__ bool  s_last;
    __shared__ double sbins[30];

    const int tid  = threadIdx.x;
    const int warp = tid >> 5;
    const int lane = tid & 31;
    const int rowBytes  = C * 4;
    const unsigned tileBytes = (unsigned)(TROWS * rowBytes);
    const int C4 = C >> 2;
    const bool tma_ok = ((C & 3) == 0) && (C4 >= 1) && (C4 <= 32);

    // Label-dtype probe (warp 0): int64 interpretation out of [0,C) proves
    // int32 (random int32 pairs form values >= 2^32 w.h.p.). Deterministic.
    if (warp == 0) {
        const long long* p = (const long long*)labels;
        int P = N / 2; if (P > 256) P = 256;
        bool bad = false;
        for (int i = lane; i < P; i += 32) {
            long long v = p[i];
            if (v < 0 || v >= (long long)C) bad = true;
        }
        unsigned any_bad = __ballot_sync(0xffffffffu, bad);
        if (lane == 0) s_lab64 = any_bad ? 0 : 1;
    }
    {
        float* z = &sb[0][0][0];
        for (int i = tid; i < CW * 8 * 30; i += NTHR) z[i] = 0.0f;
    }
    if (tid == 0) {
        #pragma unroll
        for (int s = 0; s < STAGES; s++) {
            mbar_init(s2u(&mb_full[s]), 1);     // producer expect_tx arrival
            mbar_init(s2u(&mb_empty[s]), CW);   // CW consumer warps
        }
    }
    __syncthreads();

    const int lab64 = s_lab64;
    const int nTiles = tma_ok ? (N / TROWS) : 0;

    if (tma_ok) {
        if (warp == CW) {
            // ---- Producer ----
            if (lane == 0) {
                int slot = 0, phase = 1;  // first empty-wait passes immediately
                for (int tile = blockIdx.x; tile < nTiles; tile += gridDim.x) {
                    mbar_wait(s2u(&mb_empty[slot]), (unsigned)phase);
                    unsigned fb = s2u(&mb_full[slot]);
                    mbar_expect_tx(fb, tileBytes);
                    bulk_g2s_ef(s2u(ring) + slot * tileBytes,
                                logits + (size_t)tile * TROWS * C, tileBytes, fb);
                    if (++slot == STAGES) { slot = 0; phase ^= 1; }
                }
            }
        } else {
            // ---- Consumers (warps 0..CW-1): 8 rows each ----
            const bool owner = (lane < 8);
            float* myslice = sb[warp][lane & 7];
            const int loff = (lane < C4) ? (lane << 4) : 0;   // byte offset in row
            int slot = 0, phase = 0;

            for (int tile = blockIdx.x; tile < nTiles; tile += gridDim.x) {
                // Prefetch labels before the barrier wait (latency overlap).
                int lab = 0;
                if (owner) {
                    size_t row = (size_t)tile * TROWS + warp * 8 + lane;
                    if (lab64) lab = (int)((const long long*)labels)[row];
                    else       lab = ((const int*)labels)[row];
                }

                mbar_wait(s2u(&mb_full[slot]), (unsigned)phase);
                const char* buf = ring + slot * tileBytes + warp * 8 * rowBytes;

                unsigned uk = 0;
                #pragma unroll
                for (int r = 0; r < 8; r++) {
                    float4 x = *reinterpret_cast<const float4*>(buf + r * rowBytes + loff);
                    float lv = fmaxf(fmaxf(x.x, x.y), fmaxf(x.z, x.w));
                    unsigned um = __reduce_max_sync(0xffffffffu, f2ord(lv));
                    if (lane == r) uk = um;
                }
                // Gather label logit straight from SMEM (row is resident).
                float glv = 0.0f;
                if (owner)
                    glv = *reinterpret_cast<const float*>(buf + lane * rowBytes + lab * 4);

                __syncwarp();
                if (lane == 0) mbar_arrive(s2u(&mb_empty[slot]));

                if (owner) {
                    float vmax = ord2f(uk);
                    float conf = __expf(vmax);
                    int bin = (int)ceilf(conf * 10.0f) - 1;
                    if (bin >= 0 && bin < 10) {
                        myslice[bin * 3 + 0] += 1.0f;
                        myslice[bin * 3 + 1] += conf;
                        myslice[bin * 3 + 2] += (glv == vmax) ? 1.0f : 0.0f;
                    }
                }
                if (++slot == STAGES) { slot = 0; phase ^= 1; }
            }
        }

        // Tail rows (N % TROWS) via the global path, all warps.
        const int warpsTotal = gridDim.x * (CW + 1);
        const int gwarp = blockIdx.x * (CW + 1) + warp;
        const int loff2 = (lane < C4) ? lane : 0;
        for (int row = nTiles * TROWS + gwarp; row < N; row += warpsTotal) {
            const float4* p = reinterpret_cast<const float4*>(logits + (size_t)row * C);
            float4 xx = p[loff2];
            float lv = fmaxf(fmaxf(xx.x, xx.y), fmaxf(xx.z, xx.w));
            unsigned um = __reduce_max_sync(0xffffffffu, f2ord(lv));
            if (lane == 0) {
                float vmax = ord2f(um);
                float conf = __expf(vmax);
                int bin = (int)ceilf(conf * 10.0f) - 1;
                if (bin >= 0 && bin < 10) {
                    int lab;
                    if (lab64) lab = (int)((const long long*)labels)[row];
                    else       lab = ((const int*)labels)[row];
                    float lval = __ldg(logits + (size_t)row * C + lab);
                    sb[warp % CW][0][bin * 3 + 0] += 1.0f;
                    sb[warp % CW][0][bin * 3 + 1] += conf;
                    sb[warp % CW][0][bin * 3 + 2] += (lval == vmax) ? 1.0f : 0.0f;
                }
            }
        }
    } else {
        // Generic fallback: warp per row, exact first-occurrence argmax.
        const int warpsTotal = gridDim.x * (CW + 1);
        const int gwarp = blockIdx.x * (CW + 1) + warp;
        for (int row = gwarp; row < N; row += warpsTotal) {
            float lv = -INFINITY; int li = 0x7fffffff;
            const float* p = logits + (size_t)row * C;
            for (int c = lane; c < C; c += 32) {
                float xx = p[c];
                if (xx > lv) { lv = xx; li = c; }
            }
            unsigned u  = f2ord(lv);
            unsigned um = __reduce_max_sync(0xffffffffu, u);
            unsigned cand = (u == um) ? (unsigned)li : 0xffffffffu;
            int ii = (int)__reduce_min_sync(0xffffffffu, cand);
            if (lane == 0) {
                float vv = ord2f(um);
                float conf = __expf(vv);
                int bin = (int)ceilf(conf * 10.0f) - 1;
                if (bin >= 0 && bin < 10) {
                    int lab;
                    if (lab64) lab = (int)((const long long*)labels)[row];
                    else       lab = ((const int*)labels)[row];
                    sb[warp % CW][0][bin * 3 + 0] += 1.0f;
                    sb[warp % CW][0][bin * 3 + 1] += conf;
                    sb[warp % CW][0][bin * 3 + 2] += (ii == lab) ? 1.0f : 0.0f;
                }
            }
        }
    }

    __syncthreads();

    // Block reduce CW*8 slices -> transposed per-block partials.
    if (tid < 30) {
        float s = 0.0f;
        #pragma unroll
        for (int w = 0; w < CW; w++)
            #pragma unroll
            for (int r = 0; r < 8; r++)
                s += sb[w][r][tid];
        g_part[tid * MAXB + blockIdx.x] = s;
    }

    // Last-block-done: atomicInc wraps at gridDim.x-1 -> auto-reset per launch.
    if (tid == 0) {
        __threadfence();
        unsigned old = atomicInc(&g_count, gridDim.x - 1);
        s_last = (old == gridDim.x - 1);
    }
    __syncthreads();

    if (s_last) {
        const int nb = gridDim.x;
        for (int c = warp; c < 30; c += (CW + 1)) {
            double s = 0.0;
            const float* pc = &g_part[c * MAXB];
            for (int i = lane; i < nb; i += 32) s += (double)pc[i];
            #pragma unroll
            for (int o = 16; o; o >>= 1)
                s += __shfl_down_sync(0xffffffffu, s, o);
            if (lane == 0) sbins[c] = s;
        }
        __syncthreads();

        if (tid == 0) {
            double ece = 0.0, n = (double)N;
            #pragma unroll
            for (int b = 0; b < 10; b++) {
                double cnt = sbins[b * 3 + 0];
                double sc  = sbins[b * 3 + 1];
                double sa  = sbins[b * 3 + 2];
                if (cnt > 0.0) ece += fabs(sc / cnt - sa / cnt) * (cnt / n);
            }
            out[0] = (float)ece;
        }
    }
}

extern "C" void kernel_launch(void* const* d_in, const int* in_sizes, int n_in,
                              void* d_out, int out_size)
{
    // Logits is the (much) larger buffer.
    int li = 0, bi = 1;
    if (in_sizes[1] > in_sizes[0]) { li = 1; bi = 0; }

    const float* logits = (const float*)d_in[li];
    const void*  labels = d_in[bi];

    int N = in_sizes[bi];
    int C = in_sizes[li] / N;

    bool tma_ok = ((C & 3) == 0) && (C >= 4) && (C <= 128) &&
                  ((size_t)STAGES * TROWS * C * 4 <= 208 * 1024);
    int smemBytes = tma_ok ? (STAGES * TROWS * C * 4) : 0;

    static int attr_set = -1;
    if (attr_set != smemBytes) {
        cudaFuncSetAttribute(ece_tma_kernel,
                             cudaFuncAttributeMaxDynamicSharedMemorySize,
                             smemBytes);
        attr_set = smemBytes;
    }

    int blocks = 148;   // 1 block/SM: 204.8 KB ring, 4 big tiles in flight
    long long maxBlocks = tma_ok ? (((long long)N + TROWS - 1) / TROWS)
                                 : (((long long)N + CW) / (CW + 1));
    if (blocks > maxBlocks) blocks = (int)(maxBlocks > 0 ? maxBlocks : 1);
    if (blocks < 1) blocks = 1;
    if (blocks > MAXB) blocks = MAXB;

    ece_tma_kernel<<<blocks, NTHR, smemBytes>>>(logits, labels, (float*)d_out, N, C);
}

// round 17
// speedup vs baseline: 1.1906x; 1.0163x over previous
#include <cuda_runtime.h>
#include <math.h>

#define MAXB    4096
#define STAGES  2
#define CW      30           // consumer warps per block (8 rows each)
#define TROWS   (CW * 8)     // 240 rows per tile (96 KB @ C=100)
#define NTHR    ((CW + 1) * 32)

// Per-block partials, transposed: g_part[component*MAXB + block].
__device__ float    g_part[30 * MAXB];
__device__ unsigned g_count = 0;   // auto-resets via atomicInc wrap

__device__ __forceinline__ unsigned f2ord(float f) {
    unsigned b = __float_as_uint(f);
    return b ^ ((unsigned)((int)b >> 31) | 0x80000000u);
}
__device__ __forceinline__ float ord2f(unsigned u) {
    return __uint_as_float(u ^ ((unsigned)((int)(~u) >> 31) | 0x80000000u));
}
__device__ __forceinline__ unsigned s2u(const void* p) {
    return (unsigned)__cvta_generic_to_shared(p);
}
__device__ __forceinline__ void mbar_init(unsigned mbar, unsigned cnt) {
    asm volatile("mbarrier.init.shared.b64 [%0], %1;" :: "r"(mbar), "r"(cnt) : "memory");
}
__device__ __forceinline__ void mbar_expect_tx(unsigned mbar, unsigned bytes) {
    asm volatile("mbarrier.arrive.expect_tx.shared.b64 _, [%0], %1;" :: "r"(mbar), "r"(bytes) : "memory");
}
__device__ __forceinline__ void mbar_arrive(unsigned mbar) {
    asm volatile("mbarrier.arrive.shared.b64 _, [%0];" :: "r"(mbar) : "memory");
}
__device__ __forceinline__ void mbar_wait(unsigned mbar, unsigned phase) {
    asm volatile(
        "{\n\t.reg .pred P;\n\t"
        "WL_%=:\n\t"
        "mbarrier.try_wait.parity.acquire.cta.shared::cta.b64 P, [%0], %1, 0x989680;\n\t"
        "@P bra.uni WD_%=;\n\t"
        "bra.uni WL_%=;\n\t"
        "WD_%=:\n\t}"
        :: "r"(mbar), "r"(phase) : "memory");
}
// Bulk copy with L2 evict-first hint: read-once stream must not evict the
// small reused arrays (labels, partials) from L2 across graph replays.
__device__ __forceinline__ void bulk_g2s_ef(unsigned dst, const void* src, unsigned bytes, unsigned mbar) {
    asm volatile(
        "{\n\t.reg .b64 pol;\n\t"
        "createpolicy.fractional.L2::evict_first.b64 pol, 1.0;\n\t"
        "cp.async.bulk.shared::cluster.global.mbarrier::complete_tx::bytes.L2::cache_hint "
        "[%0], [%1], %2, [%3], pol;\n\t}"
        :: "r"(dst), "l"(src), "r"(bytes), "r"(mbar) : "memory");
}

// Warp-specialized fused kernel. Warp CW = TMA producer filling a 2-stage
// SMEM ring with 240-row (96 KB) tiles; warps 0..CW-1 consume 8 rows each.
// conf = exp(row max); acc: logits[row,lab] == max (exact duplicate row
// maxima are measure-zero for continuous log-softmax data). Per-lane private
// smem bin slices; per-block partials; last-done block reduces, writes ECE.
__global__ __launch_bounds__(NTHR) void ece_tma_kernel(
    const float* __restrict__ logits,
    const void*  __restrict__ labels,
    float* __restrict__ out,
    int N, int C)
{
    extern __shared__ char ring[];                 // STAGES * tileBytes
    __shared__ unsigned long long mb_full[STAGES], mb_empty[STAGES];
    __shared__ float sb[CW][8][30];                // [warp][owner lane][component]
    __shared__ int   s_lab64;
    __shared__ bool  s_last;
    __shared__ double sbins[30];

    const int tid  = threadIdx.x;
    const int warp = tid >> 5;
    const int lane = tid & 31;
    const int rowBytes  = C * 4;
    const unsigned tileBytes = (unsigned)(TROWS * rowBytes);
    const int C4 = C >> 2;
    const bool tma_ok = ((C & 3) == 0) && (C4 >= 1) && (C4 <= 32);

    // Label-dtype probe (warp 0): int64 interpretation out of [0,C) proves
    // int32 (random int32 pairs form values >= 2^32 w.h.p.). Deterministic.
    if (warp == 0) {
        const long long* p = (const long long*)labels;
        int P = N / 2; if (P > 256) P = 256;
        bool bad = false;
        for (int i = lane; i < P; i += 32) {
            long long v = p[i];
            if (v < 0 || v >= (long long)C) bad = true;
        }
        unsigned any_bad = __ballot_sync(0xffffffffu, bad);
        if (lane == 0) s_lab64 = any_bad ? 0 : 1;
    }
    {
        float* z = &sb[0][0][0];
        for (int i = tid; i < CW * 8 * 30; i += NTHR) z[i] = 0.0f;
    }
    if (tid == 0) {
        #pragma unroll
        for (int s = 0; s < STAGES; s++) {
            mbar_init(s2u(&mb_full[s]), 1);     // producer expect_tx arrival
            mbar_init(s2u(&mb_empty[s]), CW);   // CW consumer warps
        }
    }
    __syncthreads();

    const int lab64 = s_lab64;
    const int nTiles = tma_ok ? (N / TROWS) : 0;

    if (tma_ok) {
        if (warp == CW) {
            // ---- Producer ----
            if (lane == 0) {
                int slot = 0, phase = 1;  // first empty-wait passes immediately
                for (int tile = blockIdx.x; tile < nTiles; tile += gridDim.x) {
                    mbar_wait(s2u(&mb_empty[slot]), (unsigned)phase);
                    unsigned fb = s2u(&mb_full[slot]);
                    mbar_expect_tx(fb, tileBytes);
                    bulk_g2s_ef(s2u(ring) + slot * tileBytes,
                                logits + (size_t)tile * TROWS * C, tileBytes, fb);
                    if (++slot == STAGES) { slot = 0; phase ^= 1; }
                }
            }
        } else {
            // ---- Consumers (warps 0..CW-1): 8 rows each ----
            const bool owner = (lane < 8);
            float* myslice = sb[warp][lane & 7];
            const int loff = (lane < C4) ? (lane << 4) : 0;   // byte offset in row
            int slot = 0, phase = 0;

            for (int tile = blockIdx.x; tile < nTiles; tile += gridDim.x) {
                // Prefetch labels before the barrier wait (latency overlap).
                int lab = 0;
                if (owner) {
                    size_t row = (size_t)tile * TROWS + warp * 8 + lane;
                    if (lab64) lab = (int)((const long long*)labels)[row];
                    else       lab = ((const int*)labels)[row];
                }

                mbar_wait(s2u(&mb_full[slot]), (unsigned)phase);
                const char* buf = ring + slot * tileBytes + warp * 8 * rowBytes;

                unsigned uk = 0;
                #pragma unroll
                for (int r = 0; r < 8; r++) {
                    float4 x = *reinterpret_cast<const float4*>(buf + r * rowBytes + loff);
                    float lv = fmaxf(fmaxf(x.x, x.y), fmaxf(x.z, x.w));
                    unsigned um = __reduce_max_sync(0xffffffffu, f2ord(lv));
                    if (lane == r) uk = um;
                }
                // Gather label logit straight from SMEM (row is resident).
                float glv = 0.0f;
                if (owner)
                    glv = *reinterpret_cast<const float*>(buf + lane * rowBytes + lab * 4);

                __syncwarp();
                if (lane == 0) mbar_arrive(s2u(&mb_empty[slot]));

                if (owner) {
                    float vmax = ord2f(uk);
                    float conf = __expf(vmax);
                    int bin = (int)ceilf(conf * 10.0f) - 1;
                    if (bin >= 0 && bin < 10) {
                        myslice[bin * 3 + 0] += 1.0f;
                        myslice[bin * 3 + 1] += conf;
                        myslice[bin * 3 + 2] += (glv == vmax) ? 1.0f : 0.0f;
                    }
                }
                if (++slot == STAGES) { slot = 0; phase ^= 1; }
            }
        }

        // Tail rows (N % TROWS) via the global path, all warps.
        const int warpsTotal = gridDim.x * (CW + 1);
        const int gwarp = blockIdx.x * (CW + 1) + warp;
        const int loff2 = (lane < C4) ? lane : 0;
        for (int row = nTiles * TROWS + gwarp; row < N; row += warpsTotal) {
            const float4* p = reinterpret_cast<const float4*>(logits + (size_t)row * C);
            float4 xx = p[loff2];
            float lv = fmaxf(fmaxf(xx.x, xx.y), fmaxf(xx.z, xx.w));
            unsigned um = __reduce_max_sync(0xffffffffu, f2ord(lv));
            if (lane == 0) {
                float vmax = ord2f(um);
                float conf = __expf(vmax);
                int bin = (int)ceilf(conf * 10.0f) - 1;
                if (bin >= 0 && bin < 10) {
                    int lab;
                    if (lab64) lab = (int)((const long long*)labels)[row];
                    else       lab = ((const int*)labels)[row];
                    float lval = __ldg(logits + (size_t)row * C + lab);
                    sb[warp % CW][0][bin * 3 + 0] += 1.0f;
                    sb[warp % CW][0][bin * 3 + 1] += conf;
                    sb[warp % CW][0][bin * 3 + 2] += (lval == vmax) ? 1.0f : 0.0f;
                }
            }
        }
    } else {
        // Generic fallback: warp per row, exact first-occurrence argmax.
        const int warpsTotal = gridDim.x * (CW + 1);
        const int gwarp = blockIdx.x * (CW + 1) + warp;
        for (int row = gwarp; row < N; row += warpsTotal) {
            float lv = -INFINITY; int li = 0x7fffffff;
            const float* p = logits + (size_t)row * C;
            for (int c = lane; c < C; c += 32) {
                float xx = p[c];
                if (xx > lv) { lv = xx; li = c; }
            }
            unsigned u  = f2ord(lv);
            unsigned um = __reduce_max_sync(0xffffffffu, u);
            unsigned cand = (u == um) ? (unsigned)li : 0xffffffffu;
            int ii = (int)__reduce_min_sync(0xffffffffu, cand);
            if (lane == 0) {
                float vv = ord2f(um);
                float conf = __expf(vv);
                int bin = (int)ceilf(conf * 10.0f) - 1;
                if (bin >= 0 && bin < 10) {
                    int lab;
                    if (lab64) lab = (int)((const long long*)labels)[row];
                    else       lab = ((const int*)labels)[row];
                    sb[warp % CW][0][bin * 3 + 0] += 1.0f;
                    sb[warp % CW][0][bin * 3 + 1] += conf;
                    sb[warp % CW][0][bin * 3 + 2] += (ii == lab) ? 1.0f : 0.0f;
                }
            }
        }
    }

    __syncthreads();

    // Block reduce CW*8 slices -> transposed per-block partials.
    if (tid < 30) {
        float s = 0.0f;
        #pragma unroll
        for (int w = 0; w < CW; w++)
            #pragma unroll
            for (int r = 0; r < 8; r++)
                s += sb[w][r][tid];
        g_part[tid * MAXB + blockIdx.x] = s;
    }

    // Last-block-done: atomicInc wraps at gridDim.x-1 -> auto-reset per launch.
    if (tid == 0) {
        __threadfence();
        unsigned old = atomicInc(&g_count, gridDim.x - 1);
        s_last = (old == gridDim.x - 1);
    }
    __syncthreads();

    if (s_last) {
        const int nb = gridDim.x;
        for (int c = warp; c < 30; c += (CW + 1)) {
            double s = 0.0;
            const float* pc = &g_part[c * MAXB];
            for (int i = lane; i < nb; i += 32) s += (double)pc[i];
            #pragma unroll
            for (int o = 16; o; o >>= 1)
                s += __shfl_down_sync(0xffffffffu, s, o);
            if (lane == 0) sbins[c] = s;
        }
        __syncthreads();

        if (tid == 0) {
            double ece = 0.0, n = (double)N;
            #pragma unroll
            for (int b = 0; b < 10; b++) {
                double cnt = sbins[b * 3 + 0];
                double sc  = sbins[b * 3 + 1];
                double sa  = sbins[b * 3 + 2];
                if (cnt > 0.0) ece += fabs(sc / cnt - sa / cnt) * (cnt / n);
            }
            out[0] = (float)ece;
        }
    }
}

extern "C" void kernel_launch(void* const* d_in, const int* in_sizes, int n_in,
                              void* d_out, int out_size)
{
    // Logits is the (much) larger buffer.
    int li = 0, bi = 1;
    if (in_sizes[1] > in_sizes[0]) { li = 1; bi = 0; }

    const float* logits = (const float*)d_in[li];
    const void*  labels = d_in[bi];

    int N = in_sizes[bi];
    int C = in_sizes[li] / N;

    bool tma_ok = ((C & 3) == 0) && (C >= 4) && (C <= 128) &&
                  ((size_t)STAGES * TROWS * C * 4 <= 196 * 1024);
    int smemBytes = tma_ok ? (STAGES * TROWS * C * 4) : 0;

    static int attr_set = -1;
    if (attr_set != smemBytes) {
        cudaFuncSetAttribute(ece_tma_kernel,
                             cudaFuncAttributeMaxDynamicSharedMemorySize,
                             smemBytes);
        attr_set = smemBytes;
    }

    int blocks = 148;   // 1 block/SM: 187.5 KB ring, 2 big tiles in flight
    long long maxBlocks = tma_ok ? (((long long)N + TROWS - 1) / TROWS)
                                 : (((long long)N + CW) / (CW + 1));
    if (blocks > maxBlocks) blocks = (int)(maxBlocks > 0 ? maxBlocks : 1);
    if (blocks < 1) blocks = 1;
    if (blocks > MAXB) blocks = MAXB;

    ece_tma_kernel<<<blocks, NTHR, smemBytes>>>(logits, labels, (float*)d_out, N, C);
}